// round 15
// baseline (speedup 1.0000x reference)
#include <cuda_runtime.h>
#include <cuda_bf16.h>
#include <cstdint>

#define B_ 2
#define S_ 2048
#define E_ 1024
#define H_ 16
#define D_ 64
#define M_ (B_*S_)   // 4096

// ---------------- scratch (device globals; no allocations allowed) ----------
static __device__ float g_Q[(size_t)B_*H_*S_*D_];     // [B,H,S,D]
static __device__ float g_K[(size_t)B_*H_*S_*D_];
static __device__ float g_V[(size_t)B_*H_*S_*D_];
static __device__ float g_linv[(size_t)B_*H_*S_];     // 1 / softmax row sum
static __device__ float g_T[(size_t)B_*H_*S_*S_];     // 2^(scaled scores), masked
static __device__ float g_ctx[16][(size_t)M_*E_];     // per-ktile partial context
static __device__ uint2    g_Kp[(size_t)B_*H_*16*4096];   // packed K tiles (hi,lo)
static __device__ uint32_t g_VpH[(size_t)B_*H_*16*4096];  // packed V tiles hi
static __device__ uint32_t g_VpL[(size_t)B_*H_*16*4096];  // packed V tiles lo

// ===================== PTX helpers (sm_80-era only; no tcgen05) ==============
__device__ __forceinline__ uint32_t smem_u32(const void* p) {
    uint32_t a;
    asm("{ .reg .u64 t; cvta.to.shared.u64 t, %1; cvt.u32.u64 %0, t; }" : "=r"(a) : "l"(p));
    return a;
}
#define CPASYNC16(dst, src) \
    asm volatile("cp.async.cg.shared.global [%0], [%1], 16;" :: "r"(dst), "l"(src))
#define CPCOMMIT() asm volatile("cp.async.commit_group;" ::: "memory")
#define CPWAIT0()  asm volatile("cp.async.wait_group 0;" ::: "memory")

__device__ __forceinline__ uint32_t f2tf32(float x) {
    uint32_t r;
    asm("cvt.rna.tf32.f32 %0, %1;" : "=r"(r) : "f"(x));
    return r;
}
__device__ __forceinline__ float ex2f(float x) {
    float r;
    asm("ex2.approx.f32 %0, %1;" : "=f"(r) : "f"(x));
    return r;
}
__device__ __forceinline__ void mma_tf32(float* c, const uint32_t* a, const uint32_t* b) {
    asm volatile(
        "mma.sync.aligned.m16n8k8.row.col.f32.tf32.tf32.f32 "
        "{%0,%1,%2,%3}, {%4,%5,%6,%7}, {%8,%9}, {%0,%1,%2,%3};"
        : "+f"(c[0]), "+f"(c[1]), "+f"(c[2]), "+f"(c[3])
        : "r"(a[0]), "r"(a[1]), "r"(a[2]), "r"(a[3]), "r"(b[0]), "r"(b[1]));
}
__device__ __forceinline__ void mma_bf16(float* c, const uint32_t* a, uint32_t b0, uint32_t b1) {
    asm volatile(
        "mma.sync.aligned.m16n8k16.row.col.f32.bf16.bf16.f32 "
        "{%0,%1,%2,%3}, {%4,%5,%6,%7}, {%8,%9}, {%0,%1,%2,%3};"
        : "+f"(c[0]), "+f"(c[1]), "+f"(c[2]), "+f"(c[3])
        : "r"(a[0]), "r"(a[1]), "r"(a[2]), "r"(a[3]), "r"(b0), "r"(b1));
}
// packed split: (v.x, v.y) -> hi word (bf16x2) + lo residual word (bf16x2)
// cvt.rn == __float2bfloat16 rounding; bf16->f32 re-expansion via bit ops (exact)
__device__ __forceinline__ void split2(float2 v, uint32_t& hi, uint32_t& lo) {
    uint32_t h;
    asm("cvt.rn.bf16x2.f32 %0, %1, %2;" : "=r"(h) : "f"(v.y), "f"(v.x));
    float h0 = __uint_as_float(h << 16);
    float h1 = __uint_as_float(h & 0xffff0000u);
    asm("cvt.rn.bf16x2.f32 %0, %1, %2;" : "=r"(lo) : "f"(v.y - h1), "f"(v.x - h0));
    hi = h;
}
__device__ __forceinline__ uint32_t pack_bf2(float x, float y) {
    uint32_t r;
    asm("cvt.rn.bf16x2.f32 %0, %1, %2;" : "=r"(r) : "f"(y), "f"(x));
    return r;
}

// ===================== tf32 mma.sync GEMM core: out = A @ W^T + bias =========
#define BK_ 32
#define PADK 36
#define GEMM_SMEM_BYTES (2 * 2 * 128 * PADK * 4)   // 73728

template<int SCATTER>
__device__ __forceinline__ void gemm_core(uint32_t* sgm,
    const float* __restrict__ A, const float* __restrict__ W,
    const float* __restrict__ bias, float* __restrict__ out)
{
    uint32_t (*As)[128][PADK] = (uint32_t(*)[128][PADK])sgm;
    uint32_t (*Ws)[128][PADK] = (uint32_t(*)[128][PADK])(sgm + 2*128*PADK);

    const int tid = threadIdx.x;
    const int lane = tid & 31, wid = tid >> 5;
    const int wm = (wid & 3) * 32;
    const int wn = (wid >> 2) * 64;
    const int m0 = blockIdx.y * 128;
    const int n0 = blockIdx.x * 128;

    const float* Abase = A + (size_t)m0 * E_;
    const float* Wbase = W + (size_t)n0 * E_;

    const int r_ld = tid >> 1;
    const int c_ld = (tid & 1) * 16;

    float4 aR[4], wR[4];
    auto ldg_stage = [&](int it) {
        const float* Ap = Abase + (size_t)r_ld * E_ + it * BK_ + c_ld;
        const float* Wp = Wbase + (size_t)r_ld * E_ + it * BK_ + c_ld;
#pragma unroll
        for (int i = 0; i < 4; i++) {
            aR[i] = *(const float4*)(Ap + i * 4);
            wR[i] = *(const float4*)(Wp + i * 4);
        }
    };
    auto sts_stage = [&](int buf) {
#pragma unroll
        for (int i = 0; i < 4; i++) {
            uint4 ua = make_uint4(f2tf32(aR[i].x), f2tf32(aR[i].y),
                                  f2tf32(aR[i].z), f2tf32(aR[i].w));
            uint4 uw = make_uint4(f2tf32(wR[i].x), f2tf32(wR[i].y),
                                  f2tf32(wR[i].z), f2tf32(wR[i].w));
            *(uint4*)&As[buf][r_ld][c_ld + i * 4] = ua;
            *(uint4*)&Ws[buf][r_ld][c_ld + i * 4] = uw;
        }
    };

    float acc[2][8][4];
#pragma unroll
    for (int mi = 0; mi < 2; mi++)
#pragma unroll
        for (int ni = 0; ni < 8; ni++)
#pragma unroll
            for (int j = 0; j < 4; j++) acc[mi][ni][j] = 0.f;

    const int NT = E_ / BK_;
    ldg_stage(0);
    sts_stage(0);
    __syncthreads();

    const int qr = lane >> 2;
    const int qc = lane & 3;

    for (int it = 0; it < NT; it++) {
        if (it + 1 < NT) ldg_stage(it + 1);

        const int buf = it & 1;
#pragma unroll
        for (int ks = 0; ks < 4; ks++) {
            const int k0 = ks * 8;
            uint32_t a[2][4], b[8][2];
#pragma unroll
            for (int mi = 0; mi < 2; mi++) {
                const int r = wm + mi * 16 + qr;
                a[mi][0] = As[buf][r][k0 + qc];
                a[mi][1] = As[buf][r + 8][k0 + qc];
                a[mi][2] = As[buf][r][k0 + qc + 4];
                a[mi][3] = As[buf][r + 8][k0 + qc + 4];
            }
#pragma unroll
            for (int ni = 0; ni < 8; ni++) {
                const int n = wn + ni * 8 + qr;
                b[ni][0] = Ws[buf][n][k0 + qc];
                b[ni][1] = Ws[buf][n][k0 + qc + 4];
            }
#pragma unroll
            for (int mi = 0; mi < 2; mi++)
#pragma unroll
                for (int ni = 0; ni < 8; ni++)
                    mma_tf32(acc[mi][ni], a[mi], b[ni]);
        }

        if (it + 1 < NT) sts_stage((it + 1) & 1);
        __syncthreads();
    }

#pragma unroll
    for (int mi = 0; mi < 2; mi++) {
        const int r0 = m0 + wm + mi * 16 + qr;
#pragma unroll
        for (int ni = 0; ni < 8; ni++) {
            const int n = n0 + wn + ni * 8 + 2 * qc;
            const float b0 = bias[n], b1 = bias[n + 1];
            float2 v0 = make_float2(acc[mi][ni][0] + b0, acc[mi][ni][1] + b1);
            float2 v1 = make_float2(acc[mi][ni][2] + b0, acc[mi][ni][3] + b1);
            if (SCATTER) {
                const int h = n >> 6, d = n & 63;
                const int bb0 = r0 >> 11, ss0 = r0 & (S_ - 1);
                const int r1 = r0 + 8;
                const int bb1 = r1 >> 11, ss1 = r1 & (S_ - 1);
                *(float2*)(out + (((size_t)(bb0 * H_ + h) * S_ + ss0) * D_ + d)) = v0;
                *(float2*)(out + (((size_t)(bb1 * H_ + h) * S_ + ss1) * D_ + d)) = v1;
            } else {
                *(float2*)(out + (size_t)r0 * E_ + n) = v0;
                *(float2*)(out + (size_t)(r0 + 8) * E_ + n) = v1;
            }
        }
    }
}

struct QKVArgs {
    const float *A0, *A1, *A2;
    const float *W0, *W1, *W2;
    const float *b0, *b1, *b2;
    float *o0, *o1, *o2;
};

__global__ void __launch_bounds__(256, 1)
gemm_qkv_k(QKVArgs a)
{
    extern __shared__ uint32_t sgm_qkv[];
    const int z = blockIdx.z;
    const float* A = (z == 0) ? a.A0 : (z == 1) ? a.A1 : a.A2;
    const float* W = (z == 0) ? a.W0 : (z == 1) ? a.W1 : a.W2;
    const float* bias = (z == 0) ? a.b0 : (z == 1) ? a.b1 : a.b2;
    float* out = (z == 0) ? a.o0 : (z == 1) ? a.o1 : a.o2;
    gemm_core<1>(sgm_qkv, A, W, bias, out);
}

__global__ void __launch_bounds__(256, 1)
gemm_o_k(const float* __restrict__ A, const float* __restrict__ W,
         const float* __restrict__ bias, float* __restrict__ out)
{
    extern __shared__ uint32_t sgm_o[];
    gemm_core<0>(sgm_o, A, W, bias, out);
}

// ---------------- ctx0 += ctx1..ctx15 ----------------------------------------
__global__ void __launch_bounds__(256) add16_k()
{
    const size_t i = ((size_t)blockIdx.x * 256 + threadIdx.x) * 4;
    float4 x = *(const float4*)(&g_ctx[0][i]);
#pragma unroll
    for (int s = 1; s < 16; s++) {
        float4 a = *(const float4*)(&g_ctx[s][i]);
        x.x += a.x; x.y += a.y; x.z += a.z; x.w += a.w;
    }
    *(float4*)(&g_ctx[0][i]) = x;
}

// ---------------- prepack K and V tiles into bf16 hi/lo layouts --------------
__global__ void __launch_bounds__(256) prepack_kv_k()
{
    const int kt = blockIdx.x;
    const int bh = blockIdx.y;
    const int k0 = kt * 128;
    const int tid = threadIdx.x;
    const int lane = tid & 31, wid = tid >> 5;

    // ---- K pack ----
    const float* Kg = g_K + (size_t)bh * S_ * D_;
    uint2* Kp = g_Kp + ((size_t)bh * 16 + kt) * 4096;
#pragma unroll
    for (int rp = 0; rp < 2; rp++) {
        const int n = rp * 64 + (tid >> 2);
        const int q = tid & 3;
        const float* Kpp = Kg + (size_t)(k0 + n) * D_ + q * 16;
        const uint32_t sw = (uint32_t)((n & 7) << 2);
#pragma unroll
        for (int j = 0; j < 4; j++) {
            float4 v = *(const float4*)(Kpp + j * 4);
            const int w = q * 8 + j * 2;
            uint32_t h0, l0, h1, l1;
            split2(make_float2(v.x, v.y), h0, l0);
            split2(make_float2(v.z, v.w), h1, l1);
            Kp[n * 32 + (w ^ sw)]       = make_uint2(h0, l0);
            Kp[n * 32 + ((w + 1) ^ sw)] = make_uint2(h1, l1);
        }
    }

    // ---- V pack ----
    const int dv = lane + 32 * (wid & 1);
    const int k2b = (wid >> 1) * 16;
    const float* Vg = g_V + ((size_t)bh * S_ + k0) * D_ + dv;
    uint32_t* VpH = g_VpH + ((size_t)bh * 16 + kt) * 4096;
    uint32_t* VpL = g_VpL + ((size_t)bh * 16 + kt) * 4096;
#pragma unroll 4
    for (int kk = 0; kk < 16; kk++) {
        const int k2 = k2b + kk;
        float v0 = Vg[(size_t)(2 * k2) * D_];
        float v1 = Vg[(size_t)(2 * k2 + 1) * D_];
        uint32_t hi, lo;
        split2(make_float2(v0, v1), hi, lo);
        uint32_t off = k2 * 64 + (dv ^ ((k2 & 3) << 3));
        VpH[off] = hi;
        VpL[off] = lo;
    }
}

// ---------------- pass 1: QK^T via bf16x3 mma + ex2 + row-sum ----------------
#define QSCALE (0.125f * 1.4426950408889634f)

__global__ void __launch_bounds__(256) attn_exp_k(const int* __restrict__ mask)
{
    __shared__ uint2 Kt[4096];       // [n=128][w=32] packed (hi,lo), swizzled
    __shared__ float rowsum[64];

    const int tid = threadIdx.x;
    const int lane = tid & 31, wid = tid >> 5;
    const int gid = lane >> 2, tig = lane & 3;
    const int q0 = blockIdx.x * 64;
    const int h = blockIdx.y, b = blockIdx.z;
    const int bh = b * H_ + h;
    const int wm = (wid & 3) * 16;
    const int wn = (wid >> 2) * 64;

    if (tid < 64) rowsum[tid] = 0.f;

    uint32_t aH[4][4], aL[4][4];
    {
        const float* Qg = g_Q + ((size_t)bh * S_ + q0 + wm) * D_;
#pragma unroll
        for (int ks = 0; ks < 4; ks++) {
            const int d0 = ks * 16 + 2 * tig;
            float2 v00 = *(const float2*)(Qg + (size_t)gid * D_ + d0);
            float2 v10 = *(const float2*)(Qg + (size_t)(gid + 8) * D_ + d0);
            float2 v01 = *(const float2*)(Qg + (size_t)gid * D_ + d0 + 8);
            float2 v11 = *(const float2*)(Qg + (size_t)(gid + 8) * D_ + d0 + 8);
            v00.x *= QSCALE; v00.y *= QSCALE;
            v10.x *= QSCALE; v10.y *= QSCALE;
            v01.x *= QSCALE; v01.y *= QSCALE;
            v11.x *= QSCALE; v11.y *= QSCALE;
            split2(v00, aH[ks][0], aL[ks][0]);
            split2(v10, aH[ks][1], aL[ks][1]);
            split2(v01, aH[ks][2], aL[ks][2]);
            split2(v11, aH[ks][3], aL[ks][3]);
        }
    }

    float lsum0 = 0.f, lsum1 = 0.f;
    const int r0 = q0 + wm + gid;
    const int* mrow0 = mask + (size_t)b * S_ * S_ + (size_t)r0 * S_;
    float* T0 = g_T + ((size_t)bh * S_ + r0) * S_;
    const uint32_t ktb = smem_u32(Kt);

    for (int kt = 0; kt < 16; kt++) {
        const int k0 = kt * 128;
        __syncthreads();
        {   // copy pre-packed K tile (32 KB)
            const char* src = (const char*)(g_Kp + ((size_t)bh * 16 + kt) * 4096) + tid * 128;
            const uint32_t dst = ktb + tid * 128;
#pragma unroll
            for (int i = 0; i < 8; i++)
                CPASYNC16(dst + i * 16, src + i * 16);
            CPCOMMIT();
            CPWAIT0();
        }
        __syncthreads();

        float s[8][4];
#pragma unroll
        for (int ni = 0; ni < 8; ni++)
#pragma unroll
            for (int j = 0; j < 4; j++) s[ni][j] = 0.f;

#pragma unroll
        for (int ks = 0; ks < 4; ks++) {
#pragma unroll
            for (int ni = 0; ni < 8; ni++) {
                const int nl = wn + ni * 8 + gid;
                const uint32_t sw = (uint32_t)(gid << 2);
                uint2 kv0 = Kt[nl * 32 + ((ks * 8 + tig) ^ sw)];
                uint2 kv1 = Kt[nl * 32 + ((ks * 8 + tig + 4) ^ sw)];
                mma_bf16(s[ni], aH[ks], kv0.x, kv1.x);
                mma_bf16(s[ni], aH[ks], kv0.y, kv1.y);
                mma_bf16(s[ni], aL[ks], kv0.x, kv1.x);
            }
        }

#pragma unroll
        for (int ni = 0; ni < 8; ni++) {
            const int col = k0 + wn + ni * 8 + 2 * tig;
            int2 m0 = *(const int2*)(mrow0 + col);
            int2 m1 = *(const int2*)(mrow0 + 8 * S_ + col);
            float t00 = m0.x ? ex2f(s[ni][0]) : 0.f;
            float t01 = m0.y ? ex2f(s[ni][1]) : 0.f;
            float t10 = m1.x ? ex2f(s[ni][2]) : 0.f;
            float t11 = m1.y ? ex2f(s[ni][3]) : 0.f;
            *(float2*)(T0 + col)          = make_float2(t00, t01);
            *(float2*)(T0 + 8 * S_ + col) = make_float2(t10, t11);
            lsum0 += t00 + t01;
            lsum1 += t10 + t11;
        }
    }

    lsum0 += __shfl_xor_sync(0xffffffffu, lsum0, 1);
    lsum0 += __shfl_xor_sync(0xffffffffu, lsum0, 2);
    lsum1 += __shfl_xor_sync(0xffffffffu, lsum1, 1);
    lsum1 += __shfl_xor_sync(0xffffffffu, lsum1, 2);
    if (tig == 0) {
        atomicAdd(&rowsum[wm + gid], lsum0);
        atomicAdd(&rowsum[wm + 8 + gid], lsum1);
    }
    __syncthreads();
    if (tid < 64)
        g_linv[(size_t)bh * S_ + q0 + tid] = 1.0f / rowsum[tid];
}

// ---------------- pass 2: q-block 32, ktg=1, occ 3, T reg-prefetch -----------
#define PS_STRIDE 68
#define PV_SMEM (2*32*PS_STRIDE*4 + 2*4096*4)   // 50176

__global__ void __launch_bounds__(256, 3)
attn_pv_k(float* __restrict__ avg_out)
{
    extern __shared__ char smem2[];
    uint32_t* PsH = (uint32_t*)smem2;
    uint32_t* PsL = PsH + 32*PS_STRIDE;
    uint32_t* VtH = PsL + 32*PS_STRIDE;
    uint32_t* VtL = VtH + 4096;

    const int tid = threadIdx.x;
    const int lane = tid & 31, wid = tid >> 5;
    const int kt = blockIdx.x;           // ktile 0..15
    const int k0 = kt * 128;
    const int q0 = blockIdx.y * 32;
    const int b  = blockIdx.z;

    const int wm = (wid & 1) * 16;       // 2 row groups
    const int wn = (wid >> 1) * 16;      // 4 col groups (d)

    const int pr = tid >> 3;             // 0..31 (T row)
    const int pc = (tid & 7) * 4;        // col base; cols pc + 32*i, i<4

    float* ctx = &g_ctx[kt][0];
    const uint32_t vtHb = smem_u32(VtH);
    const uint32_t vtLb = smem_u32(VtL);

    float4 avg4[4];
#pragma unroll
    for (int i = 0; i < 4; i++) avg4[i] = make_float4(0.f, 0.f, 0.f, 0.f);

    // prefetch T for h = 0
    float4 t4[4];
    {
        const float* Tp = g_T + ((size_t)(b*H_ + 0)*S_ + q0 + pr)*S_ + k0;
#pragma unroll
        for (int i = 0; i < 4; i++) t4[i] = *(const float4*)(Tp + pc + 32*i);
    }

    for (int h = 0; h < H_; h++) {
        const float li = g_linv[(size_t)(b*H_ + h)*S_ + q0 + pr];

        __syncthreads();   // prev MMA done with Ps/Vt

        {   // issue async copy of pre-packed V tile (overlaps work below)
            const size_t tb = ((size_t)(b*H_ + h) * 16 + kt) * 4096;
            const char* srcH = (const char*)(g_VpH + tb) + tid * 64;
            const char* srcL = (const char*)(g_VpL + tb) + tid * 64;
#pragma unroll
            for (int i = 0; i < 4; i++) {
                CPASYNC16(vtHb + tid * 64 + i * 16, srcH + i * 16);
                CPASYNC16(vtLb + tid * 64 + i * 16, srcL + i * 16);
            }
            CPCOMMIT();
        }

        {   // T -> p from prefetched regs, avg accumulate, packed split to Ps
#pragma unroll
            for (int i = 0; i < 4; i++) {
                const int c = pc + 32*i;
                float p0 = t4[i].x * li, p1 = t4[i].y * li;
                float p2 = t4[i].z * li, p3 = t4[i].w * li;
                avg4[i].x += p0 * 0.0625f;
                avg4[i].y += p1 * 0.0625f;
                avg4[i].z += p2 * 0.0625f;
                avg4[i].w += p3 * 0.0625f;

                uint32_t ph0, pl0, ph1, pl1;
                split2(make_float2(p0, p1), ph0, pl0);
                split2(make_float2(p2, p3), ph1, pl1);
                const int wbase = pr * PS_STRIDE + (c >> 1);
                *(uint2*)&PsH[wbase] = make_uint2(ph0, ph1);
                *(uint2*)&PsL[wbase] = make_uint2(pl0, pl1);
            }
        }

        // prefetch T for next head (latency overlaps MMA + next barrier)
        if (h + 1 < H_) {
            const float* Tp = g_T + ((size_t)(b*H_ + h + 1)*S_ + q0 + pr)*S_ + k0;
#pragma unroll
            for (int i = 0; i < 4; i++) t4[i] = *(const float4*)(Tp + pc + 32*i);
        }

        CPWAIT0();
        __syncthreads();   // Ps + Vt visible

        // ---- P @ V ----
        float acc[2][4];
#pragma unroll
        for (int ni = 0; ni < 2; ni++)
#pragma unroll
            for (int j = 0; j < 4; j++) acc[ni][j] = 0.f;

#pragma unroll
        for (int ksi = 0; ksi < 8; ksi++) {
            const int rA = wm + (lane >> 2);
            const int wA = ksi * 8 + (lane & 3);
            uint32_t aH[4], aL[4];
            aH[0] = PsH[rA * PS_STRIDE + wA];
            aH[1] = PsH[(rA + 8) * PS_STRIDE + wA];
            aH[2] = PsH[rA * PS_STRIDE + wA + 4];
            aH[3] = PsH[(rA + 8) * PS_STRIDE + wA + 4];
            aL[0] = PsL[rA * PS_STRIDE + wA];
            aL[1] = PsL[(rA + 8) * PS_STRIDE + wA];
            aL[2] = PsL[rA * PS_STRIDE + wA + 4];
            aL[3] = PsL[(rA + 8) * PS_STRIDE + wA + 4];
            const int k2v = ksi * 8 + (lane & 3);
            const uint32_t sw = (uint32_t)((k2v & 3) << 3);
#pragma unroll
            for (int ni = 0; ni < 2; ni++) {
                const int n = wn + ni * 8 + (lane >> 2);
                const uint32_t off0 = k2v * 64 + (n ^ sw);
                const uint32_t off1 = off0 + 256;
                uint32_t b0H = VtH[off0], b1H = VtH[off1];
                uint32_t b0L = VtL[off0], b1L = VtL[off1];
                mma_bf16(acc[ni], aH, b0H, b1H);
                mma_bf16(acc[ni], aH, b0L, b1L);
                mma_bf16(acc[ni], aL, b0H, b1H);
            }
        }

        // write O partial for this (head, ktile)
        const int r0 = b * S_ + q0 + wm + (lane >> 2);
#pragma unroll
        for (int ni = 0; ni < 2; ni++) {
            const int n = h * 64 + wn + ni * 8 + 2 * (lane & 3);
            *(float2*)(ctx + (size_t)r0 * E_ + n)       = make_float2(acc[ni][0], acc[ni][1]);
            *(float2*)(ctx + (size_t)(r0 + 8) * E_ + n) = make_float2(acc[ni][2], acc[ni][3]);
        }
    }

    // single write of the avg patch
    {
        float* ap = avg_out + (size_t)b*S_*S_ + (size_t)(q0 + pr)*S_ + k0;
#pragma unroll
        for (int i = 0; i < 4; i++)
            *(float4*)(ap + pc + 32*i) = avg4[i];
    }
}

// ---------------- launch ----------------------------------------------------
extern "C" void kernel_launch(void* const* d_in, const int* in_sizes, int n_in,
                              void* d_out, int out_size)
{
    const float* query = (const float*)d_in[0];
    const float* key   = (const float*)d_in[1];
    const float* value = (const float*)d_in[2];
    const int*   mask  = (const int*)d_in[3];
    const float* Wq = (const float*)d_in[4];
    const float* bq = (const float*)d_in[5];
    const float* Wk = (const float*)d_in[6];
    const float* bk = (const float*)d_in[7];
    const float* Wv = (const float*)d_in[8];
    const float* bv = (const float*)d_in[9];
    const float* Wo = (const float*)d_in[10];
    const float* bo = (const float*)d_in[11];

    float* out = (float*)d_out;                      // [B,S,E]
    float* avg = out + (size_t)B_*S_*E_;             // [B,S,S]

    float *qp, *kp, *vp, *cp;
    cudaGetSymbolAddress((void**)&qp, g_Q);
    cudaGetSymbolAddress((void**)&kp, g_K);
    cudaGetSymbolAddress((void**)&vp, g_V);
    cudaGetSymbolAddress((void**)&cp, g_ctx);

    cudaFuncSetAttribute(gemm_qkv_k, cudaFuncAttributeMaxDynamicSharedMemorySize, GEMM_SMEM_BYTES);
    cudaFuncSetAttribute(gemm_o_k,   cudaFuncAttributeMaxDynamicSharedMemorySize, GEMM_SMEM_BYTES);
    cudaFuncSetAttribute(attn_pv_k,  cudaFuncAttributeMaxDynamicSharedMemorySize, PV_SMEM);

    QKVArgs qa{query, key, value, Wq, Wk, Wv, bq, bk, bv, qp, kp, vp};
    gemm_qkv_k<<<dim3(E_/128, M_/128, 3), 256, GEMM_SMEM_BYTES>>>(qa);

    prepack_kv_k<<<dim3(16, B_*H_), 256>>>();
    attn_exp_k<<<dim3(S_/64, H_, B_), 256>>>(mask);
    attn_pv_k<<<dim3(16, S_/32, B_), 256, PV_SMEM>>>(avg);

    add16_k<<<(M_*E_)/1024, 256>>>();
    gemm_o_k<<<dim3(E_/128, M_/128), 256, GEMM_SMEM_BYTES>>>(cp, Wo, bo, out);
}

// round 16
// speedup vs baseline: 1.0148x; 1.0148x over previous
#include <cuda_runtime.h>
#include <cuda_bf16.h>
#include <cstdint>

#define B_ 2
#define S_ 2048
#define E_ 1024
#define H_ 16
#define D_ 64
#define M_ (B_*S_)   // 4096

// ---------------- scratch (device globals; no allocations allowed) ----------
static __device__ float g_Q[(size_t)B_*H_*S_*D_];     // [B,H,S,D]
static __device__ float g_K[(size_t)B_*H_*S_*D_];
static __device__ float g_V[(size_t)B_*H_*S_*D_];
static __device__ float g_linv[(size_t)B_*H_*S_];     // 1 / softmax row sum
static __device__ float g_T[(size_t)B_*H_*S_*S_];     // 2^(scaled scores), masked
static __device__ float g_ctx[16][(size_t)M_*E_];     // per-ktile partial context
static __device__ uint2    g_Kp[(size_t)B_*H_*16*4096];   // packed K tiles (hi,lo)
static __device__ uint32_t g_VpH[(size_t)B_*H_*16*4096];  // packed V tiles hi
static __device__ uint32_t g_VpL[(size_t)B_*H_*16*4096];  // packed V tiles lo
static __device__ uint32_t g_Atf[3][(size_t)M_*E_];   // tf32 query/key/value
static __device__ uint32_t g_Wtf[4][(size_t)E_*E_];   // tf32 Wq,Wk,Wv,Wo
static __device__ uint32_t g_ctxT[(size_t)M_*E_];     // tf32 summed context

// ===================== PTX helpers (sm_80-era only; no tcgen05) ==============
__device__ __forceinline__ uint32_t smem_u32(const void* p) {
    uint32_t a;
    asm("{ .reg .u64 t; cvta.to.shared.u64 t, %1; cvt.u32.u64 %0, t; }" : "=r"(a) : "l"(p));
    return a;
}
#define CPASYNC16(dst, src) \
    asm volatile("cp.async.cg.shared.global [%0], [%1], 16;" :: "r"(dst), "l"(src))
#define CPCOMMIT() asm volatile("cp.async.commit_group;" ::: "memory")
#define CPWAIT0()  asm volatile("cp.async.wait_group 0;" ::: "memory")
#define CPWAIT1()  asm volatile("cp.async.wait_group 1;" ::: "memory")

__device__ __forceinline__ uint32_t f2tf32(float x) {
    uint32_t r;
    asm("cvt.rna.tf32.f32 %0, %1;" : "=r"(r) : "f"(x));
    return r;
}
__device__ __forceinline__ float ex2f(float x) {
    float r;
    asm("ex2.approx.f32 %0, %1;" : "=f"(r) : "f"(x));
    return r;
}
__device__ __forceinline__ void mma_tf32(float* c, const uint32_t* a, const uint32_t* b) {
    asm volatile(
        "mma.sync.aligned.m16n8k8.row.col.f32.tf32.tf32.f32 "
        "{%0,%1,%2,%3}, {%4,%5,%6,%7}, {%8,%9}, {%0,%1,%2,%3};"
        : "+f"(c[0]), "+f"(c[1]), "+f"(c[2]), "+f"(c[3])
        : "r"(a[0]), "r"(a[1]), "r"(a[2]), "r"(a[3]), "r"(b[0]), "r"(b[1]));
}
__device__ __forceinline__ void mma_bf16(float* c, const uint32_t* a, uint32_t b0, uint32_t b1) {
    asm volatile(
        "mma.sync.aligned.m16n8k16.row.col.f32.bf16.bf16.f32 "
        "{%0,%1,%2,%3}, {%4,%5,%6,%7}, {%8,%9}, {%0,%1,%2,%3};"
        : "+f"(c[0]), "+f"(c[1]), "+f"(c[2]), "+f"(c[3])
        : "r"(a[0]), "r"(a[1]), "r"(a[2]), "r"(a[3]), "r"(b0), "r"(b1));
}
// packed split: (v.x, v.y) -> hi word (bf16x2) + lo residual word (bf16x2)
__device__ __forceinline__ void split2(float2 v, uint32_t& hi, uint32_t& lo) {
    uint32_t h;
    asm("cvt.rn.bf16x2.f32 %0, %1, %2;" : "=r"(h) : "f"(v.y), "f"(v.x));
    float h0 = __uint_as_float(h << 16);
    float h1 = __uint_as_float(h & 0xffff0000u);
    asm("cvt.rn.bf16x2.f32 %0, %1, %2;" : "=r"(lo) : "f"(v.y - h1), "f"(v.x - h0));
    hi = h;
}

// ===================== tf32 -> gmem prepack (cvt.rna once per element) =======
struct CvtArgs {
    const float* s[7];
    uint32_t* d[7];
    int n[7];
};
__global__ void __launch_bounds__(256) cvt_k(CvtArgs a)
{
    const int z = blockIdx.y;
    const int i = (blockIdx.x * 256 + threadIdx.x) * 4;
    if (i >= a.n[z]) return;
    float4 v = *(const float4*)(a.s[z] + i);
    uint4 u = make_uint4(f2tf32(v.x), f2tf32(v.y), f2tf32(v.z), f2tf32(v.w));
    *(uint4*)(a.d[z] + i) = u;
}

// ===================== pipelined tf32 GEMM: out = A @ W^T + bias =============
// A, W already tf32 bit-patterns in gmem. 3-stage cp.async pipeline, no CVT.
#define PADK 36
#define GSTAGE_WORDS (2 * 128 * PADK)
#define GEMM_SMEM_BYTES (3 * GSTAGE_WORDS * 4)   // 110592

template<int SCATTER>
__device__ __forceinline__ void gemm_core(uint32_t* sg,
    const uint32_t* __restrict__ A, const uint32_t* __restrict__ W,
    const float* __restrict__ bias, float* __restrict__ out)
{
    const int tid = threadIdx.x;
    const int lane = tid & 31, wid = tid >> 5;
    const int wm = (wid & 3) * 32;
    const int wn = (wid >> 2) * 64;
    const int m0 = blockIdx.y * 128;
    const int n0 = blockIdx.x * 128;

    const uint32_t* Ab = A + (size_t)m0 * E_;
    const uint32_t* Wb = W + (size_t)n0 * E_;

    const int r_ld = tid >> 1;
    const int c_ld = (tid & 1) * 16;

    auto issue = [&](int it) {
        const int s = it % 3;
        const uint32_t da = smem_u32(sg + s * GSTAGE_WORDS + r_ld * PADK + c_ld);
        const uint32_t dw = da + 128 * PADK * 4;
        const uint32_t* Ap = Ab + (size_t)r_ld * E_ + it * 32 + c_ld;
        const uint32_t* Wp = Wb + (size_t)r_ld * E_ + it * 32 + c_ld;
#pragma unroll
        for (int j = 0; j < 4; j++) {
            CPASYNC16(da + j * 16, Ap + j * 4);
            CPASYNC16(dw + j * 16, Wp + j * 4);
        }
        CPCOMMIT();
    };

    float acc[2][8][4];
#pragma unroll
    for (int mi = 0; mi < 2; mi++)
#pragma unroll
        for (int ni = 0; ni < 8; ni++)
#pragma unroll
            for (int j = 0; j < 4; j++) acc[mi][ni][j] = 0.f;

    const int NT = E_ / 32;   // 32
    issue(0);
    issue(1);

    const int qr = lane >> 2;
    const int qc = lane & 3;

    for (int it = 0; it < NT; it++) {
        if (it + 1 < NT) CPWAIT1(); else CPWAIT0();
        __syncthreads();
        if (it + 2 < NT) issue(it + 2);

        uint32_t (*As)[PADK] = (uint32_t(*)[PADK])(sg + (it % 3) * GSTAGE_WORDS);
        uint32_t (*Ws)[PADK] = As + 128;

#pragma unroll
        for (int ks = 0; ks < 4; ks++) {
            const int k0 = ks * 8;
            uint32_t a[2][4], b[8][2];
#pragma unroll
            for (int mi = 0; mi < 2; mi++) {
                const int r = wm + mi * 16 + qr;
                a[mi][0] = As[r][k0 + qc];
                a[mi][1] = As[r + 8][k0 + qc];
                a[mi][2] = As[r][k0 + qc + 4];
                a[mi][3] = As[r + 8][k0 + qc + 4];
            }
#pragma unroll
            for (int ni = 0; ni < 8; ni++) {
                const int n = wn + ni * 8 + qr;
                b[ni][0] = Ws[n][k0 + qc];
                b[ni][1] = Ws[n][k0 + qc + 4];
            }
#pragma unroll
            for (int mi = 0; mi < 2; mi++)
#pragma unroll
                for (int ni = 0; ni < 8; ni++)
                    mma_tf32(acc[mi][ni], a[mi], b[ni]);
        }
    }

#pragma unroll
    for (int mi = 0; mi < 2; mi++) {
        const int r0 = m0 + wm + mi * 16 + qr;
#pragma unroll
        for (int ni = 0; ni < 8; ni++) {
            const int n = n0 + wn + ni * 8 + 2 * qc;
            const float b0 = bias[n], b1 = bias[n + 1];
            float2 v0 = make_float2(acc[mi][ni][0] + b0, acc[mi][ni][1] + b1);
            float2 v1 = make_float2(acc[mi][ni][2] + b0, acc[mi][ni][3] + b1);
            if (SCATTER) {
                const int h = n >> 6, d = n & 63;
                const int bb0 = r0 >> 11, ss0 = r0 & (S_ - 1);
                const int r1 = r0 + 8;
                const int bb1 = r1 >> 11, ss1 = r1 & (S_ - 1);
                *(float2*)(out + (((size_t)(bb0 * H_ + h) * S_ + ss0) * D_ + d)) = v0;
                *(float2*)(out + (((size_t)(bb1 * H_ + h) * S_ + ss1) * D_ + d)) = v1;
            } else {
                *(float2*)(out + (size_t)r0 * E_ + n) = v0;
                *(float2*)(out + (size_t)(r0 + 8) * E_ + n) = v1;
            }
        }
    }
}

struct QKVArgs {
    const float *b0, *b1, *b2;
    float *o0, *o1, *o2;
};

__global__ void __launch_bounds__(256, 2)
gemm_qkv_k(QKVArgs a)
{
    extern __shared__ uint32_t sgm_qkv[];
    const int z = blockIdx.z;
    const float* bias = (z == 0) ? a.b0 : (z == 1) ? a.b1 : a.b2;
    float* out = (z == 0) ? a.o0 : (z == 1) ? a.o1 : a.o2;
    gemm_core<1>(sgm_qkv, &g_Atf[z][0], &g_Wtf[z][0], bias, out);
}

__global__ void __launch_bounds__(256, 2)
gemm_o_k(const float* __restrict__ bias, float* __restrict__ out)
{
    extern __shared__ uint32_t sgm_o[];
    gemm_core<0>(sgm_o, g_ctxT, &g_Wtf[3][0], bias, out);
}

// ---------------- ctxT = tf32(ctx0 + ctx1 + ... + ctx15) ---------------------
__global__ void __launch_bounds__(256) add16_k()
{
    const size_t i = ((size_t)blockIdx.x * 256 + threadIdx.x) * 4;
    float4 x = *(const float4*)(&g_ctx[0][i]);
#pragma unroll
    for (int s = 1; s < 16; s++) {
        float4 a = *(const float4*)(&g_ctx[s][i]);
        x.x += a.x; x.y += a.y; x.z += a.z; x.w += a.w;
    }
    uint4 u = make_uint4(f2tf32(x.x), f2tf32(x.y), f2tf32(x.z), f2tf32(x.w));
    *(uint4*)(&g_ctxT[i]) = u;
}

// ---------------- prepack K and V tiles into bf16 hi/lo layouts --------------
__global__ void __launch_bounds__(256) prepack_kv_k()
{
    const int kt = blockIdx.x;
    const int bh = blockIdx.y;
    const int k0 = kt * 128;
    const int tid = threadIdx.x;
    const int lane = tid & 31, wid = tid >> 5;

    // ---- K pack ----
    const float* Kg = g_K + (size_t)bh * S_ * D_;
    uint2* Kp = g_Kp + ((size_t)bh * 16 + kt) * 4096;
#pragma unroll
    for (int rp = 0; rp < 2; rp++) {
        const int n = rp * 64 + (tid >> 2);
        const int q = tid & 3;
        const float* Kpp = Kg + (size_t)(k0 + n) * D_ + q * 16;
        const uint32_t sw = (uint32_t)((n & 7) << 2);
#pragma unroll
        for (int j = 0; j < 4; j++) {
            float4 v = *(const float4*)(Kpp + j * 4);
            const int w = q * 8 + j * 2;
            uint32_t h0, l0, h1, l1;
            split2(make_float2(v.x, v.y), h0, l0);
            split2(make_float2(v.z, v.w), h1, l1);
            Kp[n * 32 + (w ^ sw)]       = make_uint2(h0, l0);
            Kp[n * 32 + ((w + 1) ^ sw)] = make_uint2(h1, l1);
        }
    }

    // ---- V pack ----
    const int dv = lane + 32 * (wid & 1);
    const int k2b = (wid >> 1) * 16;
    const float* Vg = g_V + ((size_t)bh * S_ + k0) * D_ + dv;
    uint32_t* VpH = g_VpH + ((size_t)bh * 16 + kt) * 4096;
    uint32_t* VpL = g_VpL + ((size_t)bh * 16 + kt) * 4096;
#pragma unroll 4
    for (int kk = 0; kk < 16; kk++) {
        const int k2 = k2b + kk;
        float v0 = Vg[(size_t)(2 * k2) * D_];
        float v1 = Vg[(size_t)(2 * k2 + 1) * D_];
        uint32_t hi, lo;
        split2(make_float2(v0, v1), hi, lo);
        uint32_t off = k2 * 64 + (dv ^ ((k2 & 3) << 3));
        VpH[off] = hi;
        VpL[off] = lo;
    }
}

// ---------------- pass 1: QK^T via bf16x3 mma + ex2 + row-sum ----------------
#define QSCALE (0.125f * 1.4426950408889634f)

__global__ void __launch_bounds__(256) attn_exp_k(const int* __restrict__ mask)
{
    __shared__ uint2 Kt[4096];       // [n=128][w=32] packed (hi,lo), swizzled
    __shared__ float rowsum[64];

    const int tid = threadIdx.x;
    const int lane = tid & 31, wid = tid >> 5;
    const int gid = lane >> 2, tig = lane & 3;
    const int q0 = blockIdx.x * 64;
    const int h = blockIdx.y, b = blockIdx.z;
    const int bh = b * H_ + h;
    const int wm = (wid & 3) * 16;
    const int wn = (wid >> 2) * 64;

    if (tid < 64) rowsum[tid] = 0.f;

    uint32_t aH[4][4], aL[4][4];
    {
        const float* Qg = g_Q + ((size_t)bh * S_ + q0 + wm) * D_;
#pragma unroll
        for (int ks = 0; ks < 4; ks++) {
            const int d0 = ks * 16 + 2 * tig;
            float2 v00 = *(const float2*)(Qg + (size_t)gid * D_ + d0);
            float2 v10 = *(const float2*)(Qg + (size_t)(gid + 8) * D_ + d0);
            float2 v01 = *(const float2*)(Qg + (size_t)gid * D_ + d0 + 8);
            float2 v11 = *(const float2*)(Qg + (size_t)(gid + 8) * D_ + d0 + 8);
            v00.x *= QSCALE; v00.y *= QSCALE;
            v10.x *= QSCALE; v10.y *= QSCALE;
            v01.x *= QSCALE; v01.y *= QSCALE;
            v11.x *= QSCALE; v11.y *= QSCALE;
            split2(v00, aH[ks][0], aL[ks][0]);
            split2(v10, aH[ks][1], aL[ks][1]);
            split2(v01, aH[ks][2], aL[ks][2]);
            split2(v11, aH[ks][3], aL[ks][3]);
        }
    }

    float lsum0 = 0.f, lsum1 = 0.f;
    const int r0 = q0 + wm + gid;
    const int* mrow0 = mask + (size_t)b * S_ * S_ + (size_t)r0 * S_;
    float* T0 = g_T + ((size_t)bh * S_ + r0) * S_;
    const uint32_t ktb = smem_u32(Kt);

    for (int kt = 0; kt < 16; kt++) {
        const int k0 = kt * 128;
        __syncthreads();
        {   // copy pre-packed K tile (32 KB)
            const char* src = (const char*)(g_Kp + ((size_t)bh * 16 + kt) * 4096) + tid * 128;
            const uint32_t dst = ktb + tid * 128;
#pragma unroll
            for (int i = 0; i < 8; i++)
                CPASYNC16(dst + i * 16, src + i * 16);
            CPCOMMIT();
            CPWAIT0();
        }
        __syncthreads();

        float s[8][4];
#pragma unroll
        for (int ni = 0; ni < 8; ni++)
#pragma unroll
            for (int j = 0; j < 4; j++) s[ni][j] = 0.f;

#pragma unroll
        for (int ks = 0; ks < 4; ks++) {
#pragma unroll
            for (int ni = 0; ni < 8; ni++) {
                const int nl = wn + ni * 8 + gid;
                const uint32_t sw = (uint32_t)(gid << 2);
                uint2 kv0 = Kt[nl * 32 + ((ks * 8 + tig) ^ sw)];
                uint2 kv1 = Kt[nl * 32 + ((ks * 8 + tig + 4) ^ sw)];
                mma_bf16(s[ni], aH[ks], kv0.x, kv1.x);
                mma_bf16(s[ni], aH[ks], kv0.y, kv1.y);
                mma_bf16(s[ni], aL[ks], kv0.x, kv1.x);
            }
        }

#pragma unroll
        for (int ni = 0; ni < 8; ni++) {
            const int col = k0 + wn + ni * 8 + 2 * tig;
            int2 m0 = *(const int2*)(mrow0 + col);
            int2 m1 = *(const int2*)(mrow0 + 8 * S_ + col);
            float t00 = m0.x ? ex2f(s[ni][0]) : 0.f;
            float t01 = m0.y ? ex2f(s[ni][1]) : 0.f;
            float t10 = m1.x ? ex2f(s[ni][2]) : 0.f;
            float t11 = m1.y ? ex2f(s[ni][3]) : 0.f;
            *(float2*)(T0 + col)          = make_float2(t00, t01);
            *(float2*)(T0 + 8 * S_ + col) = make_float2(t10, t11);
            lsum0 += t00 + t01;
            lsum1 += t10 + t11;
        }
    }

    lsum0 += __shfl_xor_sync(0xffffffffu, lsum0, 1);
    lsum0 += __shfl_xor_sync(0xffffffffu, lsum0, 2);
    lsum1 += __shfl_xor_sync(0xffffffffu, lsum1, 1);
    lsum1 += __shfl_xor_sync(0xffffffffu, lsum1, 2);
    if (tig == 0) {
        atomicAdd(&rowsum[wm + gid], lsum0);
        atomicAdd(&rowsum[wm + 8 + gid], lsum1);
    }
    __syncthreads();
    if (tid < 64)
        g_linv[(size_t)bh * S_ + q0 + tid] = 1.0f / rowsum[tid];
}

// ---------------- pass 2: q-block 32, ktg=1, occ 3, T reg-prefetch -----------
#define PS_STRIDE 68
#define PV_SMEM (2*32*PS_STRIDE*4 + 2*4096*4)   // 50176

__global__ void __launch_bounds__(256, 3)
attn_pv_k(float* __restrict__ avg_out)
{
    extern __shared__ char smem2[];
    uint32_t* PsH = (uint32_t*)smem2;
    uint32_t* PsL = PsH + 32*PS_STRIDE;
    uint32_t* VtH = PsL + 32*PS_STRIDE;
    uint32_t* VtL = VtH + 4096;

    const int tid = threadIdx.x;
    const int lane = tid & 31, wid = tid >> 5;
    const int kt = blockIdx.x;           // ktile 0..15
    const int k0 = kt * 128;
    const int q0 = blockIdx.y * 32;
    const int b  = blockIdx.z;

    const int wm = (wid & 1) * 16;       // 2 row groups
    const int wn = (wid >> 1) * 16;      // 4 col groups (d)

    const int pr = tid >> 3;             // 0..31 (T row)
    const int pc = (tid & 7) * 4;        // col base; cols pc + 32*i, i<4

    float* ctx = &g_ctx[kt][0];
    const uint32_t vtHb = smem_u32(VtH);
    const uint32_t vtLb = smem_u32(VtL);

    float4 avg4[4];
#pragma unroll
    for (int i = 0; i < 4; i++) avg4[i] = make_float4(0.f, 0.f, 0.f, 0.f);

    // prefetch T for h = 0
    float4 t4[4];
    {
        const float* Tp = g_T + ((size_t)(b*H_ + 0)*S_ + q0 + pr)*S_ + k0;
#pragma unroll
        for (int i = 0; i < 4; i++) t4[i] = *(const float4*)(Tp + pc + 32*i);
    }

    for (int h = 0; h < H_; h++) {
        const float li = g_linv[(size_t)(b*H_ + h)*S_ + q0 + pr];

        __syncthreads();   // prev MMA done with Ps/Vt

        {   // issue async copy of pre-packed V tile (overlaps work below)
            const size_t tb = ((size_t)(b*H_ + h) * 16 + kt) * 4096;
            const char* srcH = (const char*)(g_VpH + tb) + tid * 64;
            const char* srcL = (const char*)(g_VpL + tb) + tid * 64;
#pragma unroll
            for (int i = 0; i < 4; i++) {
                CPASYNC16(vtHb + tid * 64 + i * 16, srcH + i * 16);
                CPASYNC16(vtLb + tid * 64 + i * 16, srcL + i * 16);
            }
            CPCOMMIT();
        }

        {   // T -> p from prefetched regs, avg accumulate, packed split to Ps
#pragma unroll
            for (int i = 0; i < 4; i++) {
                const int c = pc + 32*i;
                float p0 = t4[i].x * li, p1 = t4[i].y * li;
                float p2 = t4[i].z * li, p3 = t4[i].w * li;
                avg4[i].x += p0 * 0.0625f;
                avg4[i].y += p1 * 0.0625f;
                avg4[i].z += p2 * 0.0625f;
                avg4[i].w += p3 * 0.0625f;

                uint32_t ph0, pl0, ph1, pl1;
                split2(make_float2(p0, p1), ph0, pl0);
                split2(make_float2(p2, p3), ph1, pl1);
                const int wbase = pr * PS_STRIDE + (c >> 1);
                *(uint2*)&PsH[wbase] = make_uint2(ph0, ph1);
                *(uint2*)&PsL[wbase] = make_uint2(pl0, pl1);
            }
        }

        // prefetch T for next head (latency overlaps MMA + next barrier)
        if (h + 1 < H_) {
            const float* Tp = g_T + ((size_t)(b*H_ + h + 1)*S_ + q0 + pr)*S_ + k0;
#pragma unroll
            for (int i = 0; i < 4; i++) t4[i] = *(const float4*)(Tp + pc + 32*i);
        }

        CPWAIT0();
        __syncthreads();   // Ps + Vt visible

        // ---- P @ V ----
        float acc[2][4];
#pragma unroll
        for (int ni = 0; ni < 2; ni++)
#pragma unroll
            for (int j = 0; j < 4; j++) acc[ni][j] = 0.f;

#pragma unroll
        for (int ksi = 0; ksi < 8; ksi++) {
            const int rA = wm + (lane >> 2);
            const int wA = ksi * 8 + (lane & 3);
            uint32_t aH[4], aL[4];
            aH[0] = PsH[rA * PS_STRIDE + wA];
            aH[1] = PsH[(rA + 8) * PS_STRIDE + wA];
            aH[2] = PsH[rA * PS_STRIDE + wA + 4];
            aH[3] = PsH[(rA + 8) * PS_STRIDE + wA + 4];
            aL[0] = PsL[rA * PS_STRIDE + wA];
            aL[1] = PsL[(rA + 8) * PS_STRIDE + wA];
            aL[2] = PsL[rA * PS_STRIDE + wA + 4];
            aL[3] = PsL[(rA + 8) * PS_STRIDE + wA + 4];
            const int k2v = ksi * 8 + (lane & 3);
            const uint32_t sw = (uint32_t)((k2v & 3) << 3);
#pragma unroll
            for (int ni = 0; ni < 2; ni++) {
                const int n = wn + ni * 8 + (lane >> 2);
                const uint32_t off0 = k2v * 64 + (n ^ sw);
                const uint32_t off1 = off0 + 256;
                uint32_t b0H = VtH[off0], b1H = VtH[off1];
                uint32_t b0L = VtL[off0], b1L = VtL[off1];
                mma_bf16(acc[ni], aH, b0H, b1H);
                mma_bf16(acc[ni], aH, b0L, b1L);
                mma_bf16(acc[ni], aL, b0H, b1H);
            }
        }

        // write O partial for this (head, ktile)
        const int r0 = b * S_ + q0 + wm + (lane >> 2);
#pragma unroll
        for (int ni = 0; ni < 2; ni++) {
            const int n = h * 64 + wn + ni * 8 + 2 * (lane & 3);
            *(float2*)(ctx + (size_t)r0 * E_ + n)       = make_float2(acc[ni][0], acc[ni][1]);
            *(float2*)(ctx + (size_t)(r0 + 8) * E_ + n) = make_float2(acc[ni][2], acc[ni][3]);
        }
    }

    // single write of the avg patch
    {
        float* ap = avg_out + (size_t)b*S_*S_ + (size_t)(q0 + pr)*S_ + k0;
#pragma unroll
        for (int i = 0; i < 4; i++)
            *(float4*)(ap + pc + 32*i) = avg4[i];
    }
}

// ---------------- launch ----------------------------------------------------
extern "C" void kernel_launch(void* const* d_in, const int* in_sizes, int n_in,
                              void* d_out, int out_size)
{
    const float* query = (const float*)d_in[0];
    const float* key   = (const float*)d_in[1];
    const float* value = (const float*)d_in[2];
    const int*   mask  = (const int*)d_in[3];
    const float* Wq = (const float*)d_in[4];
    const float* bq = (const float*)d_in[5];
    const float* Wk = (const float*)d_in[6];
    const float* bk = (const float*)d_in[7];
    const float* Wv = (const float*)d_in[8];
    const float* bv = (const float*)d_in[9];
    const float* Wo = (const float*)d_in[10];
    const float* bo = (const float*)d_in[11];

    float* out = (float*)d_out;                      // [B,S,E]
    float* avg = out + (size_t)B_*S_*E_;             // [B,S,S]

    float *qp, *kp, *vp;
    uint32_t *atf, *wtf;
    cudaGetSymbolAddress((void**)&qp, g_Q);
    cudaGetSymbolAddress((void**)&kp, g_K);
    cudaGetSymbolAddress((void**)&vp, g_V);
    cudaGetSymbolAddress((void**)&atf, g_Atf);
    cudaGetSymbolAddress((void**)&wtf, g_Wtf);

    cudaFuncSetAttribute(gemm_qkv_k, cudaFuncAttributeMaxDynamicSharedMemorySize, GEMM_SMEM_BYTES);
    cudaFuncSetAttribute(gemm_o_k,   cudaFuncAttributeMaxDynamicSharedMemorySize, GEMM_SMEM_BYTES);
    cudaFuncSetAttribute(attn_pv_k,  cudaFuncAttributeMaxDynamicSharedMemorySize, PV_SMEM);

    // prepack A (q,k,v inputs) and W (4 weights) to tf32 bit patterns
    CvtArgs ca;
    ca.s[0] = query; ca.d[0] = atf;                     ca.n[0] = M_*E_;
    ca.s[1] = key;   ca.d[1] = atf + (size_t)M_*E_;     ca.n[1] = M_*E_;
    ca.s[2] = value; ca.d[2] = atf + (size_t)2*M_*E_;   ca.n[2] = M_*E_;
    ca.s[3] = Wq;    ca.d[3] = wtf;                     ca.n[3] = E_*E_;
    ca.s[4] = Wk;    ca.d[4] = wtf + (size_t)E_*E_;     ca.n[4] = E_*E_;
    ca.s[5] = Wv;    ca.d[5] = wtf + (size_t)2*E_*E_;   ca.n[5] = E_*E_;
    ca.s[6] = Wo;    ca.d[6] = wtf + (size_t)3*E_*E_;   ca.n[6] = E_*E_;
    cvt_k<<<dim3((M_*E_)/1024, 7), 256>>>(ca);

    QKVArgs qa{bq, bk, bv, qp, kp, vp};
    gemm_qkv_k<<<dim3(E_/128, M_/128, 3), 256, GEMM_SMEM_BYTES>>>(qa);

    prepack_kv_k<<<dim3(16, B_*H_), 256>>>();
    attn_exp_k<<<dim3(S_/64, H_, B_), 256>>>(mask);
    attn_pv_k<<<dim3(16, S_/32, B_), 256, PV_SMEM>>>(avg);

    add16_k<<<(M_*E_)/1024, 256>>>();
    gemm_o_k<<<dim3(E_/128, M_/128), 256, GEMM_SMEM_BYTES>>>(bo, out);
}